// round 15
// baseline (speedup 1.0000x reference)
#include <cuda_runtime.h>
#include <cuda_bf16.h>
#include <cstdint>

#define BB 32
#define LL 512
#define DD 256
#define FF 256
#define TM 64
#define NTHR 512
#define NCONV 256
#define NEXP  512
#define XP 260
#define X_ROWS 66
#define OFF_PAR 0
#define OFF_X 4096
#define OFF_VV 72832
#define V_PLANE 49152
#define SMEM_TOTAL (OFF_VV + 2 * V_PLANE)   // 171136 -> 1 CTA/SM
#define CP 260

#define VSWZ(o) ((o) ^ ((((o) >> 5) & 7) << 4))

__device__ float  g_h[BB*LL*FF];
__device__ uint8_t g_p1[96*16*2*512], g_p2[96*16*2*512];
__device__ int    g_cs[BB*LL];

__constant__ float c_AT[4][6] = {
    {1, 1, 1, 1, 1, 0}, {0, 1,-1, 2,-2, 0},
    {0, 1, 1, 4, 4, 0}, {0, 1,-1, 8,-8, 1}};
__constant__ float c_G[6][3] = {
    {0.25f, 0.f, 0.f},
    {-1.f/6.f, -1.f/6.f, -1.f/6.f}, {-1.f/6.f, 1.f/6.f, -1.f/6.f},
    {1.f/24.f, 1.f/12.f, 1.f/6.f}, {1.f/24.f, -1.f/12.f, 1.f/6.f},
    {0.f, 0.f, 1.f}};

// ---------------- ptx helpers ----------------
__device__ __forceinline__ uint32_t smem_u32(const void* p) {
    uint32_t a;
    asm("{ .reg .u64 t; cvta.to.shared.u64 t, %1; cvt.u32.u64 %0, t; }"
        : "=r"(a) : "l"(p));
    return a;
}
__device__ __forceinline__ void ldsm4(uint32_t r[4], uint32_t addr) {
    asm volatile("ldmatrix.sync.aligned.m8n8.x4.shared.b16 {%0,%1,%2,%3}, [%4];"
        : "=r"(r[0]), "=r"(r[1]), "=r"(r[2]), "=r"(r[3]) : "r"(addr));
}
__device__ __forceinline__ void mma16816(float c[4], const uint32_t a[4],
                                         uint32_t b0, uint32_t b1) {
    asm volatile(
        "mma.sync.aligned.m16n8k16.row.col.f32.bf16.bf16.f32 "
        "{%0,%1,%2,%3}, {%4,%5,%6,%7}, {%8,%9}, {%0,%1,%2,%3};"
        : "+f"(c[0]), "+f"(c[1]), "+f"(c[2]), "+f"(c[3])
        : "r"(a[0]), "r"(a[1]), "r"(a[2]), "r"(a[3]), "r"(b0), "r"(b1));
}
__device__ __forceinline__ uint32_t packbf(float a, float b) {
    __nv_bfloat16 ha = __float2bfloat16(a), hb = __float2bfloat16(b);
    return ((uint32_t)*(uint16_t*)&hb << 16) | *(uint16_t*)&ha;
}

// Transform ONE comp for one d-pair (strength-reduced B^T, verified R13).
__device__ __forceinline__ void transform_one(const float* xs, char* smem,
                                              int t, int lane, int i, int cc) {
    int d = 2 * (lane + 32 * i);
    float2 xr[6];
    #pragma unroll
    for (int j = 0; j < 6; j++)
        xr[j] = *(const float2*)(xs + (4 * t + j) * XP + d);
    int kk = d >> 4;
    uint32_t so = VSWZ((uint32_t)(t * 32 + (d & 15) * 2));
    float v0, v1;
    #pragma unroll
    for (int e = 0; e < 2; e++) {
        float x0 = e ? xr[0].y : xr[0].x;
        float x1 = e ? xr[1].y : xr[1].x;
        float x2 = e ? xr[2].y : xr[2].x;
        float x3 = e ? xr[3].y : xr[3].x;
        float x4 = e ? xr[4].y : xr[4].x;
        float x5 = e ? xr[5].y : xr[5].x;
        float t1 = x4 - 4.f * x2;
        float t2 = x3 - 4.f * x1;
        float t3 = x4 - x2;
        float t4 = x3 - x1;
        float v;
        switch (cc) {
            case 0: v = 4.f * (x0 - x2) + t3; break;
            case 1: v = t1 + t2; break;
            case 2: v = t1 - t2; break;
            case 3: v = t3 + 2.f * t4; break;
            case 4: v = t3 - 2.f * t4; break;
            default: v = 4.f * (x1 - x3) + (x5 - x3); break;
        }
        if (e) v1 = v; else v0 = v;
    }
    __nv_bfloat16 h0 = __float2bfloat16(v0);
    __nv_bfloat16 h1 = __float2bfloat16(v1);
    uint32_t hp = ((uint32_t)*(uint16_t*)&h1 << 16) | *(uint16_t*)&h0;
    uint32_t lp = packbf(v0 - __bfloat162float(h0), v1 - __bfloat162float(h1));
    uint32_t blk = (uint32_t)(cc * 16 + kk) * 512;
    *(uint32_t*)(smem + OFF_VV + blk + so) = hp;
    *(uint32_t*)(smem + OFF_VV + V_PLANE + blk + so) = lp;
}

// ---------------------------------------------------------------------------
// Fused prep: blocks 0-31 cumsum; 32-223 U pack (proven R14).
// ---------------------------------------------------------------------------
__global__ void __launch_bounds__(512)
prep_kernel(const int* __restrict__ dur,
            const float* __restrict__ w1, const float* __restrict__ w2,
            uint8_t* __restrict__ p1, uint8_t* __restrict__ p2) {
    if (blockIdx.x < 32) {
        __shared__ int s[LL];
        int t = threadIdx.x, b = blockIdx.x;
        s[t] = dur[b * LL + t];
        for (int off = 1; off < LL; off <<= 1) {
            __syncthreads();
            int v = (t >= off) ? s[t - off] : 0;
            __syncthreads();
            s[t] += v;
        }
        g_cs[b * LL + t] = s[t];
        return;
    }
    int pb = blockIdx.x - 32;
    int which = pb / 96, gs = pb % 96;
    const float* w = which ? w2 : w1;
    uint8_t* pk = which ? p2 : p1;
    int c = gs >> 4, kk = gs & 15;
    int nf = threadIdx.x >> 5, l = threadIdx.x & 31;

    uint32_t vh[4], vl[4];
    #pragma unroll
    for (int fr = 0; fr < 2; fr++)
        #pragma unroll
        for (int r = 0; r < 2; r++) {
            int f = nf * 16 + fr * 8 + (l >> 2);
            int d = kk * 16 + (l & 3) * 2 + r * 8;
            float u0 = 0.f, u1 = 0.f;
            #pragma unroll
            for (int k = 0; k < 3; k++) {
                u0 += c_G[c][k] * w[((size_t)k * DD + d) * FF + f];
                u1 += c_G[c][k] * w[((size_t)k * DD + d + 1) * FF + f];
            }
            __nv_bfloat16 h0 = __float2bfloat16(u0), h1 = __float2bfloat16(u1);
            float r0 = u0 - __bfloat162float(h0), r1 = u1 - __bfloat162float(h1);
            vh[fr * 2 + r] = ((uint32_t)*(uint16_t*)&h1 << 16) | *(uint16_t*)&h0;
            vl[fr * 2 + r] = packbf(r0, r1);
        }
    uint8_t* base = pk + (((size_t)gs * 16 + nf) * 2) * 512 + l * 16;
    *(uint4*)base         = make_uint4(vh[0], vh[1], vh[2], vh[3]);
    *(uint4*)(base + 512) = make_uint4(vl[0], vl[1], vl[2], vl[3]);
}

// ---------------------------------------------------------------------------
// Winograd F(4,3) conv, transform-pipelined mainloop. conv<false> also
// carries NEXP expand blocks (proven R14).
// ---------------------------------------------------------------------------
template <bool FUSE_LIN>
__global__ void __launch_bounds__(NTHR, 1)
conv_wino_kernel(const float* __restrict__ in,
                 const uint8_t* __restrict__ u_pk,
                 const float* __restrict__ bias,
                 const float* __restrict__ lng, const float* __restrict__ lnb,
                 const float* __restrict__ lw, const float* __restrict__ lb,
                 float* __restrict__ out_h,
                 float* __restrict__ dur_out,
                 const float* __restrict__ xfull,
                 float* __restrict__ exp_out, int M) {
    extern __shared__ char smem[];

    // ===== expand blocks (conv1 launch only) =====
    if (!FUSE_LIN && blockIdx.x >= NCONV) {
        int eb = blockIdx.x - NCONV;
        int b = eb & 31;
        int chunk = eb >> 5;
        int* cs = (int*)smem;
        for (int i = threadIdx.x; i < LL; i += NTHR) cs[i] = g_cs[b * LL + i];
        __syncthreads();
        int warp = threadIdx.x >> 5, lane = threadIdx.x & 31;
        int total = cs[LL - 1];
        #pragma unroll
        for (int fi = 0; fi < 16; fi++) {
            int frame = chunk * 256 + warp * 16 + fi;
            int lo = 0, hi = LL;
            while (lo < hi) {
                int mid = (lo + hi) >> 1;
                if (cs[mid] > frame) hi = mid; else lo = mid + 1;
            }
            int idx = lo < (LL - 1) ? lo : (LL - 1);
            bool valid = frame < total;
            const float4* src =
                (const float4*)(xfull + ((size_t)b * LL + idx) * DD);
            float4* dst = (float4*)(exp_out + ((size_t)b * M + frame) * DD);
            float4 z = make_float4(0.f, 0.f, 0.f, 0.f);
            dst[lane]      = valid ? src[lane]      : z;
            dst[lane + 32] = valid ? src[lane + 32] : z;
        }
        return;
    }

    // ===== conv blocks =====
    const uint32_t sa = smem_u32(smem);
    const int tid  = threadIdx.x;
    const int lane = tid & 31;
    const int wid  = tid >> 5;
    const int b    = blockIdx.x >> 3;
    const int l0   = (blockIdx.x & 7) * TM;

    float* bias_s = (float*)(smem + OFF_PAR);
    float* g_s    = (float*)(smem + OFF_PAR + 1024);
    float* bl_s   = (float*)(smem + OFF_PAR + 2048);
    float* lw_s   = (float*)(smem + OFF_PAR + 3072);
    if (tid < FF) {
        bias_s[tid] = bias[tid];
        g_s[tid]    = lng[tid];
        bl_s[tid]   = lnb[tid];
        if (FUSE_LIN) lw_s[tid] = lw[tid];
    }

    // phase 1: x tile -> smem
    {
        const float4 z4 = make_float4(0.f, 0.f, 0.f, 0.f);
        float* xs = (float*)(smem + OFF_X);
        for (int u = tid; u < X_ROWS * 64; u += NTHR) {
            int row = u >> 6, p = u & 63;
            int l = l0 + row - 1;
            bool valid = (l >= 0 && l < LL);
            float4 v = valid
                ? *(const float4*)(in + ((size_t)b * LL + l) * DD + p * 4) : z4;
            *(float4*)(xs + row * XP + p * 4) = v;
        }
    }
    __syncthreads();

    // transform comp 0 only, then start the MMA stream
    const float* xs = (const float*)(smem + OFF_X);
    {
        #pragma unroll
        for (int i = 0; i < 4; i++)
            transform_one(xs, smem, wid, lane, i, 0);
    }
    __syncthreads();

    float y[4][2][4];
    #pragma unroll
    for (int i = 0; i < 4; i++)
        #pragma unroll
        for (int nb = 0; nb < 2; nb++)
            #pragma unroll
            for (int q = 0; q < 4; q++) y[i][nb][q] = 0.f;

    const uint32_t aswz = VSWZ((uint32_t)((lane & 15) * 32 + (lane >> 4) * 16));
    const uint32_t vbase = sa + OFF_VV;
    const uint8_t* uw = u_pk + (size_t)wid * 1024 + lane * 16;

    uint4 bufh[2], bufl[2];
    bufh[0] = *(const uint4*)(uw);
    bufl[0] = *(const uint4*)(uw + 512);
    bufh[1] = *(const uint4*)(uw + 16384);
    bufl[1] = *(const uint4*)(uw + 16384 + 512);

    #pragma unroll
    for (int c = 0; c < 6; c++) {
        float z[2][4];
        #pragma unroll
        for (int nb = 0; nb < 2; nb++)
            #pragma unroll
            for (int q = 0; q < 4; q++) z[nb][q] = 0.f;

        #pragma unroll
        for (int kk = 0; kk < 16; kk++) {
            const int gs = c * 16 + kk;
            uint4 bh = bufh[gs & 1], bl = bufl[gs & 1];
            if (gs < 94) {
                const uint8_t* p = uw + (size_t)(gs + 2) * 16384;
                bufh[gs & 1] = *(const uint4*)p;
                bufl[gs & 1] = *(const uint4*)(p + 512);
            }
            uint32_t ah[4], al[4];
            ldsm4(ah, vbase + gs * 512 + aswz);
            ldsm4(al, vbase + V_PLANE + gs * 512 + aswz);
            mma16816(z[0], ah, bh.x, bh.y);
            mma16816(z[1], ah, bh.z, bh.w);
            mma16816(z[0], ah, bl.x, bl.y);
            mma16816(z[1], ah, bl.z, bl.w);
            mma16816(z[0], al, bh.x, bh.y);
            mma16816(z[1], al, bh.z, bh.w);
            // pipelined transform of comp c+1 in the MMA-throttle gaps
            if (c < 5 && kk < 4)
                transform_one(xs, smem, wid, lane, kk, c + 1);
        }
        #pragma unroll
        for (int i = 0; i < 4; i++) {
            float at = c_AT[i][c];
            #pragma unroll
            for (int nb = 0; nb < 2; nb++)
                #pragma unroll
                for (int q = 0; q < 4; q++) y[i][nb][q] += at * z[nb][q];
        }
        if (c < 5) __syncthreads();   // V(c+1) writes visible before reads
    }

    // epilogue: y (+bias) -> C overlaying x
    __syncthreads();
    float* Cs = (float*)(smem + OFF_X);
    {
        const int t1 = lane >> 2;
        #pragma unroll
        for (int nb = 0; nb < 2; nb++) {
            int n = wid * 16 + nb * 8 + (lane & 3) * 2;
            float b0 = bias_s[n], b1 = bias_s[n + 1];
            #pragma unroll
            for (int i = 0; i < 4; i++) {
                int r1 = 4 * t1 + i, r2 = 4 * (t1 + 8) + i;
                *(float2*)&Cs[r1 * CP + n] =
                    make_float2(y[i][nb][0] + b0, y[i][nb][1] + b1);
                *(float2*)&Cs[r2 * CP + n] =
                    make_float2(y[i][nb][2] + b0, y[i][nb][3] + b1);
            }
        }
    }
    __syncthreads();

    // LayerNorm (+ReLU): 8 threads/row
    {
        const int r = tid >> 3;
        const int q = tid & 7;
        const float* crow = &Cs[r * CP + q * 32];
        float sum = 0.f, sq = 0.f;
        #pragma unroll
        for (int i = 0; i < 32; i++) {
            float v = crow[i];
            sum += v;
            sq  += v * v;
        }
        #pragma unroll
        for (int o = 1; o < 8; o <<= 1) {
            sum += __shfl_xor_sync(0xFFFFFFFFu, sum, o);
            sq  += __shfl_xor_sync(0xFFFFFFFFu, sq, o);
        }
        float mu   = sum * (1.f / FF);
        float rstd = rsqrtf(sq * (1.f / FF) - mu * mu + 1e-5f);

        const size_t row_g = (size_t)b * LL + l0 + r;
        if (!FUSE_LIN) {
            float* oh = out_h + row_g * FF + q * 32;
            #pragma unroll
            for (int i = 0; i < 32; i++) {
                int f = q * 32 + i;
                oh[i] = fmaxf((crow[i] - mu) * rstd * g_s[f] + bl_s[f], 0.f);
            }
        } else {
            float dot = 0.f;
            #pragma unroll
            for (int i = 0; i < 32; i++) {
                int f = q * 32 + i;
                float h = fmaxf((crow[i] - mu) * rstd * g_s[f] + bl_s[f], 0.f);
                dot += h * lw_s[f];
            }
            #pragma unroll
            for (int o = 1; o < 8; o <<= 1)
                dot += __shfl_xor_sync(0xFFFFFFFFu, dot, o);
            if (q == 0) dur_out[row_g] = fmaxf(dot + lb[0], 0.f);
        }
    }
}

// ---------------------------------------------------------------------------
extern "C" void kernel_launch(void* const* d_in, const int* in_sizes, int n_in,
                              void* d_out, int out_size) {
    const float* x    = (const float*)d_in[0];
    const int*   dur  = (const int*)  d_in[1];
    const float* c1w  = (const float*)d_in[3];
    const float* c1b  = (const float*)d_in[4];
    const float* ln1g = (const float*)d_in[5];
    const float* ln1b = (const float*)d_in[6];
    const float* c2w  = (const float*)d_in[7];
    const float* c2b  = (const float*)d_in[8];
    const float* ln2g = (const float*)d_in[9];
    const float* ln2b = (const float*)d_in[10];
    const float* lw   = (const float*)d_in[11];
    const float* lb   = (const float*)d_in[12];

    float* out = (float*)d_out;
    int M = (out_size - BB * LL) / (BB * DD);   // 4096
    float* dur_pred = out + (size_t)BB * M * DD;

    float* hbuf;
    uint8_t *p1, *p2;
    cudaGetSymbolAddress((void**)&hbuf, g_h);
    cudaGetSymbolAddress((void**)&p1, g_p1);
    cudaGetSymbolAddress((void**)&p2, g_p2);

    cudaFuncSetAttribute(conv_wino_kernel<false>,
                         cudaFuncAttributeMaxDynamicSharedMemorySize, SMEM_TOTAL);
    cudaFuncSetAttribute(conv_wino_kernel<true>,
                         cudaFuncAttributeMaxDynamicSharedMemorySize, SMEM_TOTAL);

    // fused prep: cumsum (32 blocks) + U pack (192 blocks)
    prep_kernel<<<224, 512>>>(dur, c1w, c2w, p1, p2);

    // conv1 + expand fused
    conv_wino_kernel<false><<<NCONV + NEXP, NTHR, SMEM_TOTAL>>>(
        x, p1, c1b, ln1g, ln1b, nullptr, nullptr, hbuf, nullptr,
        x, out, M);

    // conv2 (fused linear head)
    conv_wino_kernel<true><<<NCONV, NTHR, SMEM_TOTAL>>>(
        hbuf, p2, c2b, ln2g, ln2b, lw, lb, nullptr, dur_pred,
        nullptr, nullptr, M);
}

// round 16
// speedup vs baseline: 1.0239x; 1.0239x over previous
#include <cuda_runtime.h>
#include <cuda_bf16.h>
#include <cstdint>

#define BB 32
#define LL 512
#define DD 256
#define FF 256
#define TM 64
#define NTHR 512
#define NCONV 256
#define NPACK 96
#define NEXP  512
#define GRID_TOTAL (NCONV + NPACK + NEXP + NCONV)   // 1120
#define XP 260
#define X_ROWS 66
#define OFF_PAR 0
#define OFF_X 4096
#define OFF_VV 72832
#define V_PLANE 49152
#define SMEM_TOTAL (OFF_VV + 2 * V_PLANE)   // 171136 -> 1 CTA/SM
#define CP 260

#define VSWZ(o) ((o) ^ ((((o) >> 5) & 7) << 4))

__device__ float  g_h[BB*LL*FF];
__device__ uint8_t g_p1[96*16*2*512], g_p2[96*16*2*512];
__device__ int    g_cs[BB*LL];
__device__ int    g_flags[NCONV + 1];     // [0..255] conv1 tiles, [256] p2 counter

__constant__ float c_AT[4][6] = {
    {1, 1, 1, 1, 1, 0}, {0, 1,-1, 2,-2, 0},
    {0, 1, 1, 4, 4, 0}, {0, 1,-1, 8,-8, 1}};
__constant__ float c_G[6][3] = {
    {0.25f, 0.f, 0.f},
    {-1.f/6.f, -1.f/6.f, -1.f/6.f}, {-1.f/6.f, 1.f/6.f, -1.f/6.f},
    {1.f/24.f, 1.f/12.f, 1.f/6.f}, {1.f/24.f, -1.f/12.f, 1.f/6.f},
    {0.f, 0.f, 1.f}};

// ---------------- ptx helpers ----------------
__device__ __forceinline__ uint32_t smem_u32(const void* p) {
    uint32_t a;
    asm("{ .reg .u64 t; cvta.to.shared.u64 t, %1; cvt.u32.u64 %0, t; }"
        : "=r"(a) : "l"(p));
    return a;
}
__device__ __forceinline__ void ldsm4(uint32_t r[4], uint32_t addr) {
    asm volatile("ldmatrix.sync.aligned.m8n8.x4.shared.b16 {%0,%1,%2,%3}, [%4];"
        : "=r"(r[0]), "=r"(r[1]), "=r"(r[2]), "=r"(r[3]) : "r"(addr));
}
__device__ __forceinline__ void mma16816(float c[4], const uint32_t a[4],
                                         uint32_t b0, uint32_t b1) {
    asm volatile(
        "mma.sync.aligned.m16n8k16.row.col.f32.bf16.bf16.f32 "
        "{%0,%1,%2,%3}, {%4,%5,%6,%7}, {%8,%9}, {%0,%1,%2,%3};"
        : "+f"(c[0]), "+f"(c[1]), "+f"(c[2]), "+f"(c[3])
        : "r"(a[0]), "r"(a[1]), "r"(a[2]), "r"(a[3]), "r"(b0), "r"(b1));
}
__device__ __forceinline__ uint32_t packbf(float a, float b) {
    __nv_bfloat16 ha = __float2bfloat16(a), hb = __float2bfloat16(b);
    return ((uint32_t)*(uint16_t*)&hb << 16) | *(uint16_t*)&ha;
}

// ---------------- U pack body (proven R12-R14) ----------------
__device__ __forceinline__ void pack_body(int gs, const float* __restrict__ w,
                                          uint8_t* __restrict__ pk, int tid) {
    int c = gs >> 4, kk = gs & 15;
    int nf = tid >> 5, l = tid & 31;
    uint32_t vh[4], vl[4];
    #pragma unroll
    for (int fr = 0; fr < 2; fr++)
        #pragma unroll
        for (int r = 0; r < 2; r++) {
            int f = nf * 16 + fr * 8 + (l >> 2);
            int d = kk * 16 + (l & 3) * 2 + r * 8;
            float u0 = 0.f, u1 = 0.f;
            #pragma unroll
            for (int k = 0; k < 3; k++) {
                u0 += c_G[c][k] * w[((size_t)k * DD + d) * FF + f];
                u1 += c_G[c][k] * w[((size_t)k * DD + d + 1) * FF + f];
            }
            __nv_bfloat16 h0 = __float2bfloat16(u0), h1 = __float2bfloat16(u1);
            float r0 = u0 - __bfloat162float(h0), r1 = u1 - __bfloat162float(h1);
            vh[fr * 2 + r] = ((uint32_t)*(uint16_t*)&h1 << 16) | *(uint16_t*)&h0;
            vl[fr * 2 + r] = packbf(r0, r1);
        }
    uint8_t* base = pk + (((size_t)gs * 16 + nf) * 2) * 512 + l * 16;
    *(uint4*)base         = make_uint4(vh[0], vh[1], vh[2], vh[3]);
    *(uint4*)(base + 512) = make_uint4(vl[0], vl[1], vl[2], vl[3]);
}

// ---------------- prep1: cumsum (32) + p1 pack (96) ----------------
__global__ void __launch_bounds__(512)
prep1_kernel(const int* __restrict__ dur, const float* __restrict__ w1,
             uint8_t* __restrict__ p1) {
    if (blockIdx.x < 32) {
        __shared__ int s[LL];
        int t = threadIdx.x, b = blockIdx.x;
        s[t] = dur[b * LL + t];
        for (int off = 1; off < LL; off <<= 1) {
            __syncthreads();
            int v = (t >= off) ? s[t - off] : 0;
            __syncthreads();
            s[t] += v;
        }
        g_cs[b * LL + t] = s[t];
        return;
    }
    pack_body(blockIdx.x - 32, w1, p1, threadIdx.x);
}

__global__ void clear_flags_kernel() {
    if (threadIdx.x <= NCONV) g_flags[threadIdx.x] = 0;
}

// ---------------------------------------------------------------------------
// Conv body (R14 design, verbatim math). role: set_flag (conv1) sets its
// tile flag after h writes; conv2 callers wait before calling.
// ---------------------------------------------------------------------------
__device__ void conv_body(int cid, bool fuse_lin, char* smem,
                          const float* __restrict__ in,
                          const uint8_t* __restrict__ u_pk,
                          const float* __restrict__ bias,
                          const float* __restrict__ lng,
                          const float* __restrict__ lnb,
                          const float* __restrict__ lw,
                          const float* __restrict__ lb,
                          float* __restrict__ out_h,
                          float* __restrict__ dur_out) {
    const uint32_t sa = smem_u32(smem);
    const int tid  = threadIdx.x;
    const int lane = tid & 31;
    const int wid  = tid >> 5;
    const int b    = cid >> 3;
    const int l0   = (cid & 7) * TM;

    float* bias_s = (float*)(smem + OFF_PAR);
    float* g_s    = (float*)(smem + OFF_PAR + 1024);
    float* bl_s   = (float*)(smem + OFF_PAR + 2048);
    float* lw_s   = (float*)(smem + OFF_PAR + 3072);
    if (tid < FF) {
        bias_s[tid] = bias[tid];
        g_s[tid]    = lng[tid];
        bl_s[tid]   = lnb[tid];
        if (fuse_lin) lw_s[tid] = lw[tid];
    }

    // phase 1: x tile -> smem
    {
        const float4 z4 = make_float4(0.f, 0.f, 0.f, 0.f);
        float* xs = (float*)(smem + OFF_X);
        for (int u = tid; u < X_ROWS * 64; u += NTHR) {
            int row = u >> 6, p = u & 63;
            int l = l0 + row - 1;
            bool valid = (l >= 0 && l < LL);
            float4 v = valid
                ? *(const float4*)(in + ((size_t)b * LL + l) * DD + p * 4) : z4;
            *(float4*)(xs + row * XP + p * 4) = v;
        }
    }
    __syncthreads();

    // phase 2: V transform (strength-reduced B^T) -> swizzled smem
    {
        const float* xs = (const float*)(smem + OFF_X);
        const int t = tid >> 5;
        #pragma unroll
        for (int i = 0; i < 4; i++) {
            int d = 2 * (lane + 32 * i);
            float2 xr[6];
            #pragma unroll
            for (int j = 0; j < 6; j++)
                xr[j] = *(const float2*)(xs + (4 * t + j) * XP + d);
            int kk = d >> 4;
            uint32_t so = VSWZ((uint32_t)(t * 32 + (d & 15) * 2));

            float v[6][2];
            #pragma unroll
            for (int e = 0; e < 2; e++) {
                float x0 = e ? xr[0].y : xr[0].x;
                float x1 = e ? xr[1].y : xr[1].x;
                float x2 = e ? xr[2].y : xr[2].x;
                float x3 = e ? xr[3].y : xr[3].x;
                float x4 = e ? xr[4].y : xr[4].x;
                float x5 = e ? xr[5].y : xr[5].x;
                float t1 = x4 - 4.f * x2;
                float t2 = x3 - 4.f * x1;
                float t3 = x4 - x2;
                float t4 = x3 - x1;
                v[0][e] = 4.f * (x0 - x2) + t3;
                v[1][e] = t1 + t2;
                v[2][e] = t1 - t2;
                v[3][e] = t3 + 2.f * t4;
                v[4][e] = t3 - 2.f * t4;
                v[5][e] = 4.f * (x1 - x3) + (x5 - x3);
            }
            #pragma unroll
            for (int c = 0; c < 6; c++) {
                float v0 = v[c][0], v1 = v[c][1];
                __nv_bfloat16 h0 = __float2bfloat16(v0);
                __nv_bfloat16 h1 = __float2bfloat16(v1);
                uint32_t hp = ((uint32_t)*(uint16_t*)&h1 << 16) | *(uint16_t*)&h0;
                uint32_t lp = packbf(v0 - __bfloat162float(h0),
                                     v1 - __bfloat162float(h1));
                uint32_t blk = (uint32_t)(c * 16 + kk) * 512;
                *(uint32_t*)(smem + OFF_VV + blk + so) = hp;
                *(uint32_t*)(smem + OFF_VV + V_PLANE + blk + so) = lp;
            }
        }
    }
    __syncthreads();

    // phase 3: barrier-free mainloop
    float y[4][2][4];
    #pragma unroll
    for (int i = 0; i < 4; i++)
        #pragma unroll
        for (int nb = 0; nb < 2; nb++)
            #pragma unroll
            for (int q = 0; q < 4; q++) y[i][nb][q] = 0.f;

    const uint32_t aswz = VSWZ((uint32_t)((lane & 15) * 32 + (lane >> 4) * 16));
    const uint32_t vbase = sa + OFF_VV;
    const uint8_t* uw = u_pk + (size_t)wid * 1024 + lane * 16;

    uint4 bufh[2], bufl[2];
    bufh[0] = *(const uint4*)(uw);
    bufl[0] = *(const uint4*)(uw + 512);
    bufh[1] = *(const uint4*)(uw + 16384);
    bufl[1] = *(const uint4*)(uw + 16384 + 512);

    #pragma unroll
    for (int c = 0; c < 6; c++) {
        float z[2][4];
        #pragma unroll
        for (int nb = 0; nb < 2; nb++)
            #pragma unroll
            for (int q = 0; q < 4; q++) z[nb][q] = 0.f;

        #pragma unroll 4
        for (int kk = 0; kk < 16; kk++) {
            const int gs = c * 16 + kk;
            uint4 bh = bufh[gs & 1], bl = bufl[gs & 1];
            if (gs < 94) {
                const uint8_t* p = uw + (size_t)(gs + 2) * 16384;
                bufh[gs & 1] = *(const uint4*)p;
                bufl[gs & 1] = *(const uint4*)(p + 512);
            }
            uint32_t ah[4], al[4];
            ldsm4(ah, vbase + gs * 512 + aswz);
            ldsm4(al, vbase + V_PLANE + gs * 512 + aswz);
            mma16816(z[0], ah, bh.x, bh.y);
            mma16816(z[1], ah, bh.z, bh.w);
            mma16816(z[0], ah, bl.x, bl.y);
            mma16816(z[1], ah, bl.z, bl.w);
            mma16816(z[0], al, bh.x, bh.y);
            mma16816(z[1], al, bh.z, bh.w);
        }
        #pragma unroll
        for (int i = 0; i < 4; i++) {
            float at = c_AT[i][c];
            #pragma unroll
            for (int nb = 0; nb < 2; nb++)
                #pragma unroll
                for (int q = 0; q < 4; q++) y[i][nb][q] += at * z[nb][q];
        }
    }

    // phase 4: epilogue — y (+bias) -> C overlaying x
    __syncthreads();
    float* Cs = (float*)(smem + OFF_X);
    {
        const int t1 = lane >> 2;
        #pragma unroll
        for (int nb = 0; nb < 2; nb++) {
            int n = wid * 16 + nb * 8 + (lane & 3) * 2;
            float b0 = bias_s[n], b1 = bias_s[n + 1];
            #pragma unroll
            for (int i = 0; i < 4; i++) {
                int r1 = 4 * t1 + i, r2 = 4 * (t1 + 8) + i;
                *(float2*)&Cs[r1 * CP + n] =
                    make_float2(y[i][nb][0] + b0, y[i][nb][1] + b1);
                *(float2*)&Cs[r2 * CP + n] =
                    make_float2(y[i][nb][2] + b0, y[i][nb][3] + b1);
            }
        }
    }
    __syncthreads();

    // LayerNorm (+ReLU): 8 threads/row
    {
        const int r = tid >> 3;
        const int q = tid & 7;
        const float* crow = &Cs[r * CP + q * 32];
        float sum = 0.f, sq = 0.f;
        #pragma unroll
        for (int i = 0; i < 32; i++) {
            float v = crow[i];
            sum += v;
            sq  += v * v;
        }
        #pragma unroll
        for (int o = 1; o < 8; o <<= 1) {
            sum += __shfl_xor_sync(0xFFFFFFFFu, sum, o);
            sq  += __shfl_xor_sync(0xFFFFFFFFu, sq, o);
        }
        float mu   = sum * (1.f / FF);
        float rstd = rsqrtf(sq * (1.f / FF) - mu * mu + 1e-5f);

        const size_t row_g = (size_t)b * LL + l0 + r;
        if (!fuse_lin) {
            float* oh = out_h + row_g * FF + q * 32;
            #pragma unroll
            for (int i = 0; i < 32; i++) {
                int f = q * 32 + i;
                oh[i] = fmaxf((crow[i] - mu) * rstd * g_s[f] + bl_s[f], 0.f);
            }
        } else {
            float dot = 0.f;
            #pragma unroll
            for (int i = 0; i < 32; i++) {
                int f = q * 32 + i;
                float h = fmaxf((crow[i] - mu) * rstd * g_s[f] + bl_s[f], 0.f);
                dot += h * lw_s[f];
            }
            #pragma unroll
            for (int o = 1; o < 8; o <<= 1)
                dot += __shfl_xor_sync(0xFFFFFFFFu, dot, o);
            if (q == 0) dur_out[row_g] = fmaxf(dot + lb[0], 0.f);
        }
    }

    // conv1: publish tile flag (release)
    if (!fuse_lin) {
        __threadfence();
        __syncthreads();
        if (tid == 0) atomicExch(&g_flags[cid], 1);
    }
}

// ---------------------------------------------------------------------------
// Mega kernel: conv1 | pack-p2 | expand | conv2 (flag-dependent).
// ---------------------------------------------------------------------------
__global__ void __launch_bounds__(NTHR, 1)
mega_kernel(const float* __restrict__ x,
            const float* __restrict__ w2,
            const uint8_t* __restrict__ p1, uint8_t* __restrict__ p2,
            const float* __restrict__ c1b,
            const float* __restrict__ ln1g, const float* __restrict__ ln1b,
            const float* __restrict__ c2b,
            const float* __restrict__ ln2g, const float* __restrict__ ln2b,
            const float* __restrict__ lw, const float* __restrict__ lb,
            float* __restrict__ hbuf, float* __restrict__ exp_out,
            float* __restrict__ dur_pred, int M) {
    extern __shared__ char smem[];
    const int bid = blockIdx.x;
    const int tid = threadIdx.x;

    if (bid < NCONV) {
        // conv1
        conv_body(bid, false, smem, x, p1, c1b, ln1g, ln1b,
                  nullptr, nullptr, hbuf, nullptr);
        return;
    }
    if (bid < NCONV + NPACK) {
        // pack p2
        pack_body(bid - NCONV, w2, p2, tid);
        __threadfence();
        __syncthreads();
        if (tid == 0) atomicAdd(&g_flags[NCONV], 1);
        return;
    }
    if (bid < NCONV + NPACK + NEXP) {
        // expand (proven R14)
        int eb = bid - NCONV - NPACK;
        int b = eb & 31;
        int chunk = eb >> 5;
        int* cs = (int*)smem;
        for (int i = tid; i < LL; i += NTHR) cs[i] = g_cs[b * LL + i];
        __syncthreads();
        int warp = tid >> 5, lane = tid & 31;
        int total = cs[LL - 1];
        #pragma unroll
        for (int fi = 0; fi < 16; fi++) {
            int frame = chunk * 256 + warp * 16 + fi;
            int lo = 0, hi = LL;
            while (lo < hi) {
                int mid = (lo + hi) >> 1;
                if (cs[mid] > frame) hi = mid; else lo = mid + 1;
            }
            int idx = lo < (LL - 1) ? lo : (LL - 1);
            bool valid = frame < total;
            const float4* src = (const float4*)(x + ((size_t)b * LL + idx) * DD);
            float4* dst = (float4*)(exp_out + ((size_t)b * M + frame) * DD);
            float4 z = make_float4(0.f, 0.f, 0.f, 0.f);
            dst[lane]      = valid ? src[lane]      : z;
            dst[lane + 32] = valid ? src[lane + 32] : z;
        }
        return;
    }

    // conv2: wait for p2 + neighbor h tiles, then run
    {
        int cid = bid - NCONV - NPACK - NEXP;     // 0..255
        if (tid == 0) {
            while (atomicAdd(&g_flags[NCONV], 0) < NPACK) __nanosleep(200);
            int bb = cid >> 3, lt = cid & 7;
            #pragma unroll
            for (int dl = -1; dl <= 1; dl++) {
                int l2 = min(max(lt + dl, 0), 7);
                while (atomicAdd(&g_flags[bb * 8 + l2], 0) == 0) __nanosleep(200);
            }
            __threadfence();
        }
        __syncthreads();
        conv_body(cid, true, smem, hbuf, p2, c2b, ln2g, ln2b,
                  lw, lb, nullptr, dur_pred);
    }
}

// ---------------------------------------------------------------------------
extern "C" void kernel_launch(void* const* d_in, const int* in_sizes, int n_in,
                              void* d_out, int out_size) {
    const float* x    = (const float*)d_in[0];
    const int*   dur  = (const int*)  d_in[1];
    const float* c1w  = (const float*)d_in[3];
    const float* c1b  = (const float*)d_in[4];
    const float* ln1g = (const float*)d_in[5];
    const float* ln1b = (const float*)d_in[6];
    const float* c2w  = (const float*)d_in[7];
    const float* c2b  = (const float*)d_in[8];
    const float* ln2g = (const float*)d_in[9];
    const float* ln2b = (const float*)d_in[10];
    const float* lw   = (const float*)d_in[11];
    const float* lb   = (const float*)d_in[12];

    float* out = (float*)d_out;
    int M = (out_size - BB * LL) / (BB * DD);   // 4096
    float* dur_pred = out + (size_t)BB * M * DD;

    float* hbuf;
    uint8_t *p1, *p2;
    cudaGetSymbolAddress((void**)&hbuf, g_h);
    cudaGetSymbolAddress((void**)&p1, g_p1);
    cudaGetSymbolAddress((void**)&p2, g_p2);

    cudaFuncSetAttribute(mega_kernel,
                         cudaFuncAttributeMaxDynamicSharedMemorySize, SMEM_TOTAL);

    clear_flags_kernel<<<1, NCONV + 1>>>();
    prep1_kernel<<<128, 512>>>(dur, c1w, p1);

    mega_kernel<<<GRID_TOTAL, NTHR, SMEM_TOTAL>>>(
        x, c2w, p1, p2, c1b, ln1g, ln1b, c2b, ln2g, ln2b, lw, lb,
        hbuf, out, dur_pred, M);
}